// round 9
// baseline (speedup 1.0000x reference)
#include <cuda_runtime.h>
#include <cuda_fp16.h>

// M is 2000 x 20000 fp32 (fixed by setup_inputs).
#define Nn 2000
#define Mm 20000
#define ALPHA 20.0f
#define THR 0.005f
#define EPSc 1e-16f
#define NT 512
#define NBLK 148                 // one block per SM
// Pass 1 tiling: 200 col-tiles (100 cols) x 10 row-chunks (200 rows)
#define A_CT 200
#define A_TW 100
#define A_RC 10
#define A_TASKS 2000
// Fused pass: thread owns 40 columns as 5 slots of 8 (col = s*4096 + tid*8)
#define SLOT4_LIM 452            // slot 4 valid for tid < 452 (16384+452*8 = 20000)

// Static device scratch (no runtime allocation).
__device__ __half g_he[(size_t)Nn * Mm];    // exp(-20 M) fp16: 80 MB (fits L2)
__device__ float g_v[Mm];
__device__ float g_PA[A_RC * Mm];           // pass-1 column partials
__device__ float g_C[(size_t)NBLK * Mm];    // per-block K^T u partials, 11.8 MB
__device__ float g_errP[NBLK];
__device__ float g_lossP[NBLK];
__device__ int   g_cntA[A_CT];
__device__ unsigned g_barcnt = 0;

__device__ __forceinline__ unsigned ldcg_u(const unsigned* p) {
    unsigned v;
    asm volatile("ld.global.cg.u32 %0, [%1];" : "=r"(v) : "l"(p));
    return v;
}

// Grid barrier: 148 arrivals; polling uses plain L2 loads (no atomic RMW storm).
__device__ __forceinline__ void gridbar(unsigned* eps) {
    __syncthreads();
    if (threadIdx.x == 0) {
        unsigned target = *eps + NBLK;
        __threadfence();                        // release
        atomicAdd(&g_barcnt, 1u);
        while (ldcg_u(&g_barcnt) < target) __nanosleep(64);
        __threadfence();                        // acquire
        *eps = target;
    }
    __syncthreads();
}

__global__ void __launch_bounds__(NT, 1)
sinkhorn_all(const float* __restrict__ M, float* __restrict__ out) {
    const int tid = threadIdx.x;
    const int bid = blockIdx.x;
    const int tx = tid & 31, ty = tid >> 5;
    // Pass-1 map: thread owns 4 cols (fc) x 10 rows (rg); 500 active threads
    const int rg = tid / 25;                    // 0..19 when tid<500
    const int fc = tid - rg * 25;               // 0..24
    const bool actA = (tid < 500);
    // Fused-pass static rows: 2000 = 76*14 + 72*13
    const int rs = bid * 13 + min(bid, 76);
    const int re = rs + 13 + (bid < 76 ? 1 : 0);

    __shared__ float s_rT[20][A_TW];            // 8 KB pass-1 partials
    __shared__ float sA[NT];                    // 2 KB reductions
    __shared__ float sS[16], sL[16];
    __shared__ float s_bc;
    __shared__ int s_comb;
    __shared__ unsigned s_ep;

    if (tid == 0) s_ep = 0;
    __syncthreads();

    const float bm = 1.0f / (float)Mm;
    const float am = 1.0f / (float)Nn;

    // ---- Pass 1: colsum(e) -> v1 = bm/(colsum*am + eps). Streams M (__ldcs,
    //      evict-first) so the fp16 he it writes stays L2-resident. ----
    for (int task = bid; task < A_TASKS; task += NBLK) {
        const int rc = task / A_CT, ct = task - rc * A_CT;
        const int j0 = ct * A_TW;
        const int r0 = rc * 200 + rg * 10;
        if (actA) {
            float a0 = 0.f, a1 = 0.f, a2 = 0.f, a3 = 0.f;
            const float4* Mp = (const float4*)(M + (size_t)r0 * Mm + j0 + fc * 4);
            __half* Hp = g_he + (size_t)r0 * Mm + j0 + fc * 4;
            #pragma unroll
            for (int kk = 0; kk < 10; ++kk) {
                float4 m4 = __ldcs(Mp + (size_t)kk * (Mm / 4));
                float e0 = __expf(-ALPHA * m4.x);
                float e1 = __expf(-ALPHA * m4.y);
                float e2 = __expf(-ALPHA * m4.z);
                float e3 = __expf(-ALPHA * m4.w);
                a0 += e0; a1 += e1; a2 += e2; a3 += e3;
                uint2 hv;
                *(__half2*)&hv.x = __floats2half2_rn(e0, e1);
                *(__half2*)&hv.y = __floats2half2_rn(e2, e3);
                *(uint2*)(Hp + (size_t)kk * Mm) = hv;
            }
            s_rT[rg][fc * 4]     = a0;
            s_rT[rg][fc * 4 + 1] = a1;
            s_rT[rg][fc * 4 + 2] = a2;
            s_rT[rg][fc * 4 + 3] = a3;
        }
        __syncthreads();
        if (tid < A_TW) {                       // fixed-order 20-way reduce
            float T = 0.f;
            #pragma unroll
            for (int g = 0; g < 20; ++g) T += s_rT[g][tid];
            g_PA[rc * Mm + j0 + tid] = T;
        }
        __syncthreads();
        if (tid == 0) {
            __threadfence();                    // release partial
            int old = atomicAdd(&g_cntA[ct], 1);
            if (old == A_RC - 1) { __threadfence(); s_comb = 1; }
            else s_comb = 0;
        }
        __syncthreads();
        if (s_comb) {                           // last arriver: v1 for 100 cols
            if (tid < A_TW) {
                const int j = j0 + tid;
                float T = 0.f;
                #pragma unroll
                for (int rcq = 0; rcq < A_RC; ++rcq)
                    T += __ldcg(&g_PA[rcq * Mm + j]);
                g_v[j] = bm / (T * am + EPSc);
            }
            if (tid == 0) g_cntA[ct] = 0;       // reset for next replay
        }
        __syncthreads();
    }
    gridbar(&s_ep);

    // Reference: err only *updated* at cpt==1 / cpt==51 -> exit only at
    // cpt in {1,51,100}. Fused pass k: u_k = a/(K v_k); C = per-block partials
    // of K^T u_k; L_i (loss integrand) when k in {1,51,100}. Merge gives
    // err(cpt=k) = sum_j |v_k_j*(K^T u_k)_j - bm| and v_{k+1}.
    for (int k = 1; k <= 100; ++k) {
        const bool chk = (k == 1) || (k == 51);
        const bool lossk = chk || (k == 100);

        // Stage this thread's 40 v values (cols s*4096 + tid*8 .. +7).
        float vv[5][8];
        #pragma unroll
        for (int s = 0; s < 5; ++s) {
            if (s < 4 || tid < SLOT4_LIM) {
                const float* vp = g_v + s * 4096 + tid * 8;
                float4 t0 = __ldcg((const float4*)vp);
                float4 t1 = __ldcg((const float4*)(vp + 4));
                vv[s][0] = t0.x; vv[s][1] = t0.y; vv[s][2] = t0.z; vv[s][3] = t0.w;
                vv[s][4] = t1.x; vv[s][5] = t1.y; vv[s][6] = t1.z; vv[s][7] = t1.w;
            }
        }
        float CC[5][8];
        #pragma unroll
        for (int s = 0; s < 5; ++s)
            #pragma unroll
            for (int q = 0; q < 8; ++q) CC[s][q] = 0.f;
        float loss_acc = 0.f;                   // tid 0 only

        for (int r = rs; r < re; ++r) {
            const __half* rp = g_he + (size_t)r * Mm;
            uint4 hh[5];
            #pragma unroll
            for (int s = 0; s < 5; ++s)
                if (s < 4 || tid < SLOT4_LIM)
                    hh[s] = *(const uint4*)(rp + s * 4096 + tid * 8);
            float S = 0.f, L = 0.f;
            #pragma unroll
            for (int s = 0; s < 5; ++s) {
                if (s < 4 || tid < SLOT4_LIM) {
                    float2 e0 = __half22float2(*(__half2*)&hh[s].x);
                    float2 e1 = __half22float2(*(__half2*)&hh[s].y);
                    float2 e2 = __half22float2(*(__half2*)&hh[s].z);
                    float2 e3 = __half22float2(*(__half2*)&hh[s].w);
                    float p0 = e0.x * vv[s][0], p1 = e0.y * vv[s][1];
                    float p2 = e1.x * vv[s][2], p3 = e1.y * vv[s][3];
                    float p4 = e2.x * vv[s][4], p5 = e2.y * vv[s][5];
                    float p6 = e3.x * vv[s][6], p7 = e3.y * vv[s][7];
                    S += ((p0 + p1) + (p2 + p3)) + ((p4 + p5) + (p6 + p7));
                    if (lossk) {
                        L += p0 * __logf(fmaxf(e0.x, 1e-30f))
                           + p1 * __logf(fmaxf(e0.y, 1e-30f))
                           + p2 * __logf(fmaxf(e1.x, 1e-30f))
                           + p3 * __logf(fmaxf(e1.y, 1e-30f))
                           + p4 * __logf(fmaxf(e2.x, 1e-30f))
                           + p5 * __logf(fmaxf(e2.y, 1e-30f))
                           + p6 * __logf(fmaxf(e3.x, 1e-30f))
                           + p7 * __logf(fmaxf(e3.y, 1e-30f));
                    }
                }
            }
            #pragma unroll
            for (int o = 16; o > 0; o >>= 1) {
                S += __shfl_xor_sync(0xffffffffu, S, o);
                L += __shfl_xor_sync(0xffffffffu, L, o);
            }
            if (tx == 0) { sS[ty] = S; sL[ty] = L; }
            __syncthreads();
            if (tid == 0) {
                float St = 0.f, Lt = 0.f;
                #pragma unroll
                for (int w = 0; w < 16; ++w) { St += sS[w]; Lt += sL[w]; }
                float u = am / (St + EPSc);
                s_bc = u;
                if (lossk) loss_acc += u * Lt;
            }
            __syncthreads();
            const float u = s_bc;
            #pragma unroll
            for (int s = 0; s < 5; ++s) {
                if (s < 4 || tid < SLOT4_LIM) {
                    float2 e0 = __half22float2(*(__half2*)&hh[s].x);
                    float2 e1 = __half22float2(*(__half2*)&hh[s].y);
                    float2 e2 = __half22float2(*(__half2*)&hh[s].z);
                    float2 e3 = __half22float2(*(__half2*)&hh[s].w);
                    CC[s][0] = fmaf(u, e0.x, CC[s][0]);
                    CC[s][1] = fmaf(u, e0.y, CC[s][1]);
                    CC[s][2] = fmaf(u, e1.x, CC[s][2]);
                    CC[s][3] = fmaf(u, e1.y, CC[s][3]);
                    CC[s][4] = fmaf(u, e2.x, CC[s][4]);
                    CC[s][5] = fmaf(u, e2.y, CC[s][5]);
                    CC[s][6] = fmaf(u, e3.x, CC[s][6]);
                    CC[s][7] = fmaf(u, e3.y, CC[s][7]);
                }
            }
        }
        // Write per-block column partials + loss partial.
        #pragma unroll
        for (int s = 0; s < 5; ++s) {
            if (s < 4 || tid < SLOT4_LIM) {
                float* cp = g_C + (size_t)bid * Mm + s * 4096 + tid * 8;
                *(float4*)cp = make_float4(CC[s][0], CC[s][1], CC[s][2], CC[s][3]);
                *(float4*)(cp + 4) = make_float4(CC[s][4], CC[s][5], CC[s][6], CC[s][7]);
            }
        }
        if (lossk && tid == 0) g_lossP[bid] = loss_acc;
        gridbar(&s_ep);

        if (k == 100) {                         // exit without convergence
            if (bid == 0) {
                sA[tid] = (tid < NBLK) ? __ldcg(&g_lossP[tid]) : 0.f;
                __syncthreads();
                for (int o = NT / 2; o > 0; o >>= 1) {
                    if (tid < o) sA[tid] += sA[tid + o];
                    __syncthreads();
                }
                if (tid == 0) out[0] = sA[0] * (-100.0f / ALPHA);
            }
            break;
        }

        // ---- Merge: T_j = sum_b C[b][j] (fixed order); err (chk); new v ----
        {
            const int j = bid * NT + tid;
            float err = 0.f;
            if (j < Mm) {
                float T = 0.f;
                #pragma unroll 4
                for (int b = 0; b < NBLK; ++b)
                    T += __ldcg(&g_C[(size_t)b * Mm + j]);
                if (chk) err = fabsf(__ldcg(&g_v[j]) * T - bm);
                g_v[j] = bm / (T + EPSc);
            }
            if (chk) {
                sA[tid] = err;
                __syncthreads();
                for (int o = NT / 2; o > 0; o >>= 1) {
                    if (tid < o) sA[tid] += sA[tid + o];
                    __syncthreads();
                }
                if (tid == 0) g_errP[bid] = sA[0];
            }
        }
        gridbar(&s_ep);

        if (chk) {                              // redundant uniform decide
            sA[tid] = (tid < NBLK) ? __ldcg(&g_errP[tid]) : 0.f;
            __syncthreads();
            for (int o = NT / 2; o > 0; o >>= 1) {
                if (tid < o) sA[tid] += sA[tid + o];
                __syncthreads();
            }
            if (sA[0] <= THR) {
                if (bid == 0) {
                    __syncthreads();
                    sA[tid] = (tid < NBLK) ? __ldcg(&g_lossP[tid]) : 0.f;
                    __syncthreads();
                    for (int o = NT / 2; o > 0; o >>= 1) {
                        if (tid < o) sA[tid] += sA[tid + o];
                        __syncthreads();
                    }
                    if (tid == 0) out[0] = sA[0] * (-100.0f / ALPHA);
                }
                break;
            }
        }
    }

    // Final arrive: last block resets the barrier for the next graph replay.
    __syncthreads();
    if (tid == 0) {
        __threadfence();
        unsigned old = atomicAdd(&g_barcnt, 1u);
        if (old == s_ep + NBLK - 1) atomicExch(&g_barcnt, 0u);
    }
}

extern "C" void kernel_launch(void* const* d_in, const int* in_sizes, int n_in,
                              void* d_out, int out_size) {
    const float* M = (const float*)d_in[0];
    float* out = (float*)d_out;
    sinkhorn_all<<<NBLK, NT>>>(M, out);
}

// round 10
// speedup vs baseline: 1.6035x; 1.6035x over previous
#include <cuda_runtime.h>
#include <cuda_fp16.h>

// M is 2000 x 20000 fp32 (fixed by setup_inputs).
#define Nn 2000
#define Mm 20000
#define ALPHA 20.0f
#define THR 0.005f
#define EPSc 1e-16f
#define NT 256
#define NBLK 888                 // 6 x 148 SMs: all blocks co-resident
// Phase A: 200 col-tiles (100 cols) x 20 row-chunks (100 rows)
#define A_CT 200
#define A_TW 100
#define A_RC 20
#define A_TASKS (A_CT * A_RC)    // 4000
// Phase B: 500 row-groups (4 rows) x 10 col-slices (2000 cols)
#define B_GRP 500
#define B_SL 10
#define B_SW 2000
#define B_TASKS (B_GRP * B_SL)   // 5000

// Static device scratch (no runtime allocation).
__device__ __half g_he[(size_t)Nn * Mm];   // K = exp(-20 M) fp16: 80 MB
__device__ float g_u[Nn];
__device__ float g_v[Mm];
__device__ float g_PA[A_RC * Mm];          // K^T u partials (1.6 MB)
__device__ float g_PL[A_RC * Mm];          // loss-integrand partials (chk only)
__device__ float g_SB[B_SL * Nn];          // K v partials
__device__ float g_errT[A_CT];
__device__ float g_lossT[A_CT];
__device__ int   g_cntA[A_CT];
__device__ int   g_cntB[B_GRP];
__device__ unsigned g_ticket = 0;
__device__ unsigned g_barcnt = 0;

__device__ __forceinline__ unsigned ldcg_u(const unsigned* p) {
    unsigned v;
    asm volatile("ld.global.cg.u32 %0, [%1];" : "=r"(v) : "l"(p));
    return v;
}

// Grid barrier: one arrival atomic per block; polling via plain L2 loads
// (no atomic-RMW storm at the LTS). All NBLK blocks co-resident by
// construction (launch_bounds(256,6), 888 = 6*148).
__device__ __forceinline__ void gridbar(unsigned* eps) {
    __syncthreads();
    if (threadIdx.x == 0) {
        unsigned target = *eps + NBLK;
        __threadfence();                       // release
        atomicAdd(&g_barcnt, 1u);
        while (ldcg_u(&g_barcnt) < target) __nanosleep(64);
        __threadfence();                       // acquire
        *eps = target;
    }
    __syncthreads();
}

__global__ void __launch_bounds__(NT, 6)
sinkhorn_all(const float* __restrict__ M, float* __restrict__ out) {
    const int tid = threadIdx.x;
    const int bid = blockIdx.x;
    const int tx = tid & 31, ty = tid >> 5;
    // Phase-A map: thread owns 4 cols (fc) over 10 rows (row group rg)
    const int rg = tid / 25;                   // 0..9 valid when tid<250
    const int fc = tid - rg * 25;              // 0..24
    const bool actA = (tid < 250);

    __shared__ float s_u[Nn];                  // 8 KB
    __shared__ float s_rT[10][A_TW];           // 4 KB
    __shared__ float s_rL[10][A_TW];           // 4 KB (chk / post-loop only)
    __shared__ float sA[NT];
    __shared__ float s_w[8][4];                // B: per-warp row partials
    __shared__ float s_cb[B_SL][4];            // B: combine staging
    __shared__ int s_cur, s_next, s_comb;
    __shared__ unsigned s_ep;

    if (tid == 0) s_ep = 0;
    __syncthreads();

    const float bm = 1.0f / (float)Mm;
    const float am = 1.0f / (float)Nn;
    unsigned tbase = 0;
    bool conv = false;

    // Reference: err only updated at cpt==1 / cpt==51 -> exit only at
    // cpt in {1,51,100}. chk at t==2/t==52 uses v_{t-1}, K^T u_{t-1}; the
    // loss for the (u_{t-1}, v_{t-1}) exit state is computed IN the chk pass.
    for (int t = 1; t <= 100; ++t) {
        const bool chk = (t == 2) || (t == 52);

        // ---- Phase A: T = K^T u partials (+ loss integrand at chk);
        //      last-arriver per col-tile computes v (+err, +loss terms).
        //      t==1: stream M (__ldcs), write g_he. t>1: read g_he. ----
        if (t > 1) {
            for (int i = tid; i < Nn; i += NT) s_u[i] = __ldcg(&g_u[i]);
        }
        if (tid == 0) s_cur = (int)(atomicAdd(&g_ticket, 1u) - tbase);
        __syncthreads();
        int cur = s_cur;
        while (cur < A_TASKS) {
            if (tid == 255) s_next = (int)(atomicAdd(&g_ticket, 1u) - tbase);
            const int rc = cur / A_CT, ct = cur - rc * A_CT;
            const int j0 = ct * A_TW;
            const int r0 = rc * 100 + rg * 10;
            float a0 = 0.f, a1 = 0.f, a2 = 0.f, a3 = 0.f;
            float l0 = 0.f, l1 = 0.f, l2 = 0.f, l3 = 0.f;
            if (actA) {
                if (t == 1) {
                    const float4* Mp = (const float4*)(M + (size_t)r0 * Mm + j0 + fc * 4);
                    __half* Hp = g_he + (size_t)r0 * Mm + j0 + fc * 4;
                    #pragma unroll
                    for (int k = 0; k < 10; ++k) {
                        float4 m4 = __ldcs(Mp + (size_t)k * (Mm / 4));
                        float e0 = __expf(-ALPHA * m4.x);
                        float e1 = __expf(-ALPHA * m4.y);
                        float e2 = __expf(-ALPHA * m4.z);
                        float e3 = __expf(-ALPHA * m4.w);
                        a0 += e0; a1 += e1; a2 += e2; a3 += e3;
                        uint2 hv;
                        *(__half2*)&hv.x = __floats2half2_rn(e0, e1);
                        *(__half2*)&hv.y = __floats2half2_rn(e2, e3);
                        *(uint2*)(Hp + (size_t)k * Mm) = hv;
                    }
                } else if (chk) {
                    const __half* Hp = g_he + (size_t)r0 * Mm + j0 + fc * 4;
                    #pragma unroll
                    for (int k = 0; k < 10; ++k) {
                        uint2 hv = *(const uint2*)(Hp + (size_t)k * Mm);
                        float2 e01 = __half22float2(*(__half2*)&hv.x);
                        float2 e23 = __half22float2(*(__half2*)&hv.y);
                        float ui = s_u[r0 + k];
                        float p0 = e01.x * ui, p1 = e01.y * ui;
                        float p2 = e23.x * ui, p3 = e23.y * ui;
                        a0 += p0; a1 += p1; a2 += p2; a3 += p3;
                        l0 = fmaf(p0, __logf(fmaxf(e01.x, 1e-30f)), l0);
                        l1 = fmaf(p1, __logf(fmaxf(e01.y, 1e-30f)), l1);
                        l2 = fmaf(p2, __logf(fmaxf(e23.x, 1e-30f)), l2);
                        l3 = fmaf(p3, __logf(fmaxf(e23.y, 1e-30f)), l3);
                    }
                } else {
                    const __half* Hp = g_he + (size_t)r0 * Mm + j0 + fc * 4;
                    #pragma unroll
                    for (int k = 0; k < 10; ++k) {
                        uint2 hv = *(const uint2*)(Hp + (size_t)k * Mm);
                        float2 e01 = __half22float2(*(__half2*)&hv.x);
                        float2 e23 = __half22float2(*(__half2*)&hv.y);
                        float ui = s_u[r0 + k];
                        a0 = fmaf(e01.x, ui, a0); a1 = fmaf(e01.y, ui, a1);
                        a2 = fmaf(e23.x, ui, a2); a3 = fmaf(e23.y, ui, a3);
                    }
                }
                s_rT[rg][fc * 4]     = a0;
                s_rT[rg][fc * 4 + 1] = a1;
                s_rT[rg][fc * 4 + 2] = a2;
                s_rT[rg][fc * 4 + 3] = a3;
                if (chk) {
                    s_rL[rg][fc * 4]     = l0;
                    s_rL[rg][fc * 4 + 1] = l1;
                    s_rL[rg][fc * 4 + 2] = l2;
                    s_rL[rg][fc * 4 + 3] = l3;
                }
            }
            __syncthreads();
            if (tid < A_TW) {                  // fixed-order 10-way reduce
                float T = 0.f;
                #pragma unroll
                for (int g = 0; g < 10; ++g) T += s_rT[g][tid];
                g_PA[rc * Mm + j0 + tid] = T;
                if (chk) {
                    float L = 0.f;
                    #pragma unroll
                    for (int g = 0; g < 10; ++g) L += s_rL[g][tid];
                    g_PL[rc * Mm + j0 + tid] = L;
                }
            }
            __syncthreads();
            if (tid == 0) {
                __threadfence();               // release partials
                int old = atomicAdd(&g_cntA[ct], 1);
                if (old == A_RC - 1) { __threadfence(); s_comb = 1; }
                else s_comb = 0;
            }
            __syncthreads();
            if (s_comb) {                      // combine: v (+err,+loss)
                float e = 0.f, lj = 0.f;
                if (tid < A_TW) {
                    const int j = j0 + tid;
                    float T = 0.f;
                    #pragma unroll
                    for (int rcq = 0; rcq < A_RC; ++rcq)
                        T += __ldcg(&g_PA[rcq * Mm + j]);
                    if (t == 1) T *= am;
                    if (chk) {
                        float vold = __ldcg(&g_v[j]);
                        e = fabsf(vold * T - bm);
                        float LM = 0.f;
                        #pragma unroll
                        for (int rcq = 0; rcq < A_RC; ++rcq)
                            LM += __ldcg(&g_PL[rcq * Mm + j]);
                        lj = vold * LM;
                    }
                    g_v[j] = bm / (T + EPSc);
                }
                if (tid == 0) g_cntA[ct] = 0;  // reset for next use
                if (chk) {
                    sA[tid] = e;
                    __syncthreads();
                    for (int o = NT / 2; o > 0; o >>= 1) {
                        if (tid < o) sA[tid] += sA[tid + o];
                        __syncthreads();
                    }
                    if (tid == 0) g_errT[ct] = sA[0];
                    __syncthreads();
                    sA[tid] = lj;
                    __syncthreads();
                    for (int o = NT / 2; o > 0; o >>= 1) {
                        if (tid < o) sA[tid] += sA[tid + o];
                        __syncthreads();
                    }
                    if (tid == 0) g_lossT[ct] = sA[0];
                }
            }
            cur = s_next;
            __syncthreads();
        }
        tbase += A_TASKS + NBLK;
        gridbar(&s_ep);

        if (chk) {
            // Every block redundantly computes the stop decision (same
            // fixed-order sum -> identical result -> uniform break).
            sA[tid] = (tid < A_CT) ? __ldcg(&g_errT[tid]) : 0.f;
            __syncthreads();
            for (int o = NT / 2; o > 0; o >>= 1) {
                if (tid < o) sA[tid] += sA[tid + o];
                __syncthreads();
            }
            if (sA[0] <= THR) {
                if (bid == 0) {                // finalize loss, write result
                    __syncthreads();
                    sA[tid] = (tid < A_CT) ? __ldcg(&g_lossT[tid]) : 0.f;
                    __syncthreads();
                    for (int o = NT / 2; o > 0; o >>= 1) {
                        if (tid < o) sA[tid] += sA[tid + o];
                        __syncthreads();
                    }
                    if (tid == 0) out[0] = sA[0] * (-100.0f / ALPHA);
                }
                conv = true;
                break;
            }
        }

        // ---- Phase B: 4-row x 2000-col tasks; S_r = K v row partials;
        //      groups REVERSED (L2 reuse); 10th slice combines u. ----
        if (tid == 0) s_cur = (int)(atomicAdd(&g_ticket, 1u) - tbase);
        __syncthreads();
        int cur2 = s_cur;
        while (cur2 < B_TASKS) {
            if (tid == 255) s_next = (int)(atomicAdd(&g_ticket, 1u) - tbase);
            const int grp = (B_GRP - 1) - (cur2 / B_SL);   // reverse order
            const int sl = cur2 % B_SL;
            const int r0 = grp * 4;
            float S0 = 0.f, S1 = 0.f, S2 = 0.f, S3 = 0.f;
            if (tid < 250) {
                const __half* hb = g_he + (size_t)r0 * Mm + sl * B_SW + tid * 8;
                const float4* Vp = (const float4*)(g_v + sl * B_SW);
                float4 va = __ldcg(&Vp[2 * tid]);
                float4 vb = __ldcg(&Vp[2 * tid + 1]);
                #define BROW(S, r) { \
                    uint4 h = *(const uint4*)(hb + (size_t)(r) * Mm); \
                    float2 e0 = __half22float2(*(__half2*)&h.x); \
                    float2 e1 = __half22float2(*(__half2*)&h.y); \
                    float2 e2 = __half22float2(*(__half2*)&h.z); \
                    float2 e3 = __half22float2(*(__half2*)&h.w); \
                    S = (e0.x * va.x + e0.y * va.y) + (e1.x * va.z + e1.y * va.w) \
                      + (e2.x * vb.x + e2.y * vb.y) + (e3.x * vb.z + e3.y * vb.w); }
                BROW(S0, 0) BROW(S1, 1) BROW(S2, 2) BROW(S3, 3)
                #undef BROW
            }
            #pragma unroll
            for (int o = 16; o > 0; o >>= 1) {
                S0 += __shfl_xor_sync(0xffffffffu, S0, o);
                S1 += __shfl_xor_sync(0xffffffffu, S1, o);
                S2 += __shfl_xor_sync(0xffffffffu, S2, o);
                S3 += __shfl_xor_sync(0xffffffffu, S3, o);
            }
            if (tx == 0) {
                s_w[ty][0] = S0; s_w[ty][1] = S1;
                s_w[ty][2] = S2; s_w[ty][3] = S3;
            }
            __syncthreads();
            if (tid < 4) {                     // fixed-order 8-warp reduce
                float s = 0.f;
                #pragma unroll
                for (int w = 0; w < 8; ++w) s += s_w[w][tid];
                g_SB[sl * Nn + r0 + tid] = s;
            }
            __syncthreads();
            if (tid == 0) {
                __threadfence();               // release
                int old = atomicAdd(&g_cntB[grp], 1);
                if (old == B_SL - 1) { __threadfence(); s_comb = 1; }
                else s_comb = 0;
            }
            __syncthreads();
            if (s_comb) {                      // combine u for 4 rows
                if (tid < 40) {                // 40 parallel partial loads
                    const int p = tid >> 2, rl = tid & 3;
                    s_cb[p][rl] = __ldcg(&g_SB[p * Nn + r0 + rl]);
                }
                __syncthreads();
                if (tid < 4) {
                    float St = 0.f;
                    #pragma unroll
                    for (int p = 0; p < B_SL; ++p) St += s_cb[p][tid];
                    g_u[r0 + tid] = am / (St + EPSc);
                }
                if (tid == 0) g_cntB[grp] = 0; // reset for next use
            }
            cur2 = s_next;
            __syncthreads();
        }
        tbase += B_TASKS + NBLK;
        gridbar(&s_ep);
    }

    // Exit at t==100 without convergence: dedicated loss pass (u100, v100).
    if (!conv) {
        for (int i = tid; i < Nn; i += NT) s_u[i] = __ldcg(&g_u[i]);
        if (tid == 0) s_cur = (int)(atomicAdd(&g_ticket, 1u) - tbase);
        __syncthreads();
        int cur = s_cur;
        while (cur < A_TASKS) {
            if (tid == 255) s_next = (int)(atomicAdd(&g_ticket, 1u) - tbase);
            const int rc = cur / A_CT, ct = cur - rc * A_CT;
            const int j0 = ct * A_TW;
            const int r0 = rc * 100 + rg * 10;
            float l0 = 0.f, l1 = 0.f, l2 = 0.f, l3 = 0.f;
            if (actA) {
                const __half* Hp = g_he + (size_t)r0 * Mm + j0 + fc * 4;
                #pragma unroll
                for (int k = 0; k < 10; ++k) {
                    uint2 hv = *(const uint2*)(Hp + (size_t)k * Mm);
                    float2 e01 = __half22float2(*(__half2*)&hv.x);
                    float2 e23 = __half22float2(*(__half2*)&hv.y);
                    float ui = s_u[r0 + k];
                    l0 = fmaf(e01.x * ui, __logf(fmaxf(e01.x, 1e-30f)), l0);
                    l1 = fmaf(e01.y * ui, __logf(fmaxf(e01.y, 1e-30f)), l1);
                    l2 = fmaf(e23.x * ui, __logf(fmaxf(e23.x, 1e-30f)), l2);
                    l3 = fmaf(e23.y * ui, __logf(fmaxf(e23.y, 1e-30f)), l3);
                }
                s_rL[rg][fc * 4]     = l0;
                s_rL[rg][fc * 4 + 1] = l1;
                s_rL[rg][fc * 4 + 2] = l2;
                s_rL[rg][fc * 4 + 3] = l3;
            }
            __syncthreads();
            if (tid < A_TW) {
                float L = 0.f;
                #pragma unroll
                for (int g = 0; g < 10; ++g) L += s_rL[g][tid];
                g_PL[rc * Mm + j0 + tid] = L;
            }
            cur = s_next;
            __syncthreads();
        }
        gridbar(&s_ep);
        if (bid == 0) {
            float l = 0.f;
            for (int j = tid; j < Mm; j += NT) {
                float LM = 0.f;
                #pragma unroll
                for (int rc = 0; rc < A_RC; ++rc) LM += __ldcg(&g_PL[rc * Mm + j]);
                l += __ldcg(&g_v[j]) * LM;
            }
            sA[tid] = l;
            __syncthreads();
            for (int o = NT / 2; o > 0; o >>= 1) {
                if (tid < o) sA[tid] += sA[tid + o];
                __syncthreads();
            }
            if (tid == 0) out[0] = sA[0] * (-100.0f / ALPHA);
        }
    }

    // Final arrive: last block resets ticket + barrier for the next replay.
    __syncthreads();
    if (tid == 0) {
        __threadfence();
        unsigned old = atomicAdd(&g_barcnt, 1u);
        if (old == s_ep + NBLK - 1) {
            atomicExch(&g_ticket, 0u);
            atomicExch(&g_barcnt, 0u);
        }
    }
}

extern "C" void kernel_launch(void* const* d_in, const int* in_sizes, int n_in,
                              void* d_out, int out_size) {
    const float* M = (const float*)d_in[0];
    float* out = (float*)d_out;
    sinkhorn_all<<<NBLK, NT>>>(M, out);
}